// round 4
// baseline (speedup 1.0000x reference)
#include <cuda_runtime.h>
#include <cstdint>

// ---------------------------------------------------------------------------
// BatchTopK fully fused: ONE persistent kernel, 6 CTAs/SM co-resident.
//   phase 0: sampled 12-bit histogram -> guess threshold
//   phase 1: full read+write pass (zeros output, collects candidates),
//            static grid-stride chunks
//   phase 2-4: exact 3-level radix select on candidates
//   phase 5: winner scatter + EMA threshold + tie fixup
// Global state is re-zeroed at end-of-kernel for the next graph replay.
// ---------------------------------------------------------------------------

#define K_TOTAL       98304u       // 32 * 512 * 6
#define EMA_E         0.003f
#define CANDCAP       2097152u
#define EQCAP         4096u
#define SAMPLE_TARGET 1024u
#define NB            888          // 148 SMs * 6 CTAs -> co-resident
#define NT            256
#define NTHR          (NB * NT)
#define SCAP          2048u
#define CHUNK_F4      1024         // 256 threads * 4 float4

static __device__ unsigned g_hist_s[4096];
static __device__ unsigned g_histA[4096];
static __device__ unsigned g_histB[4096];
static __device__ unsigned g_hist8[256];
static __device__ unsigned g_cand_key[CANDCAP];
static __device__ unsigned g_cand_idx[CANDCAP];
static __device__ unsigned g_eq_idx[EQCAP];
static __device__ unsigned g_cand_cnt;
static __device__ unsigned g_eq_cnt;
static __device__ unsigned g_bar;     // accumulating barrier counter
static __device__ unsigned g_base;    // barrier base (advances every run)

__device__ __forceinline__ unsigned fkey(float f) {
    unsigned u = __float_as_uint(f);
    return (u & 0x80000000u) ? ~u : (u | 0x80000000u);
}
__device__ __forceinline__ float kval(unsigned k) {
    unsigned u = (k & 0x80000000u) ? (k & 0x7FFFFFFFu) : ~k;
    return __uint_as_float(u);
}

__device__ __forceinline__ void grid_bar(unsigned target) {
    __syncthreads();
    if (threadIdx.x == 0) {
        __threadfence();
        atomicAdd(&g_bar, 1u);
        int backoff = 32;
        while (atomicAdd(&g_bar, 0u) < target) {
            __nanosleep(backoff);
            if (backoff < 256) backoff <<= 1;
        }
    }
    __syncthreads();
    __threadfence();
}

// Warp-aggregated shared-memory histogram add.
__device__ __forceinline__ void wagg_add(unsigned* sh, unsigned bin, bool valid) {
    unsigned lane = threadIdx.x & 31u;
    unsigned b = valid ? bin : (0x10000u + lane);
    unsigned m = __match_any_sync(0xFFFFFFFFu, b);
    if (valid && (unsigned)(__ffs(m) - 1) == lane)
        atomicAdd(&sh[bin], (unsigned)__popc(m));
}

// Block-redundant: suffix-scan 256*PER-bin histogram; max bin with suffix >= k.
template <int PER>
__device__ void suffix_pick(const unsigned* hist, unsigned k,
                            unsigned* s_scan, unsigned* s_bin, unsigned* s_rem) {
    int t = threadIdx.x;
    unsigned p = 0;
    #pragma unroll
    for (int i = 0; i < PER; i++) p += hist[t * PER + i];
    s_scan[t] = p;
    __syncthreads();
    for (int d = 1; d < 256; d <<= 1) {
        unsigned v = (t + d < 256) ? s_scan[t + d] : 0u;
        __syncthreads();
        s_scan[t] += v;
        __syncthreads();
    }
    if (s_scan[0] < k) {
        if (t == 0) { *s_bin = 0; *s_rem = 1; }
    } else {
        bool mine = (s_scan[t] >= k) && (t == 255 || s_scan[t + 1] < k);
        if (mine) {
            unsigned running = (t == 255) ? 0u : s_scan[t + 1];
            unsigned bsel = (unsigned)(t * PER);
            unsigned rem = 1;
            for (int i = PER - 1; i >= 0; i--) {
                unsigned h = hist[t * PER + i];
                if (running + h >= k) { bsel = (unsigned)(t * PER + i); rem = k - running; break; }
                running += h;
            }
            *s_bin = bsel; *s_rem = rem;
        }
    }
    __syncthreads();
}

// ---------------------------------------------------------------------------
__global__ void __launch_bounds__(NT, 6)
k_all(const float* __restrict__ x, const float4* __restrict__ x4,
      float4* __restrict__ o4, const float* __restrict__ thr,
      float* __restrict__ out, int n, int n4, int ntot) {
    __shared__ union {
        unsigned hist[4096];
        struct { unsigned key[SCAP]; unsigned idx[SCAP]; } st;
    } u;
    __shared__ unsigned s_scan[256];
    __shared__ unsigned s_bin, s_rem, s_cnt, s_gbase;

    const int t = threadIdx.x;
    const unsigned gid = blockIdx.x * NT + t;
    const unsigned base = g_base;

    // ---------------- Phase 0: sampled histogram -> guess ----------------
    for (int i = t; i < 4096; i += NT) u.hist[i] = 0;
    __syncthreads();
    int nsamp = n >> 8;                        // sample every 256th element
    int sit = (nsamp + NTHR - 1) / NTHR;
    for (int s = 0; s < sit; s++) {
        int j = (int)gid + s * NTHR;
        bool v = j < nsamp;
        unsigned bin = v ? (fkey(x[(size_t)j << 8]) >> 20) : 0u;
        wagg_add(u.hist, bin, v);
    }
    __syncthreads();
    for (int i = t; i < 4096; i += NT) {
        unsigned c = u.hist[i];
        if (c) atomicAdd(&g_hist_s[i], c);
    }
    grid_bar(base + NB);                                         // bar1
    suffix_pick<16>(g_hist_s, SAMPLE_TARGET, s_scan, &s_bin, &s_rem);
    const float gf = kval(s_bin << 20);

    // ---------------- Phase 1: full pass (static grid-stride chunks) -----
    if (t == 0) s_cnt = 0;
    __syncthreads();
    const int nchunks = (n4 + CHUNK_F4 - 1) / CHUNK_F4;
    const float4 z4 = make_float4(0.f, 0.f, 0.f, 0.f);
    for (int ch = blockIdx.x; ch < nchunks; ch += NB) {
        int bbase = ch * CHUNK_F4 + t;
        float4 v[4];
        if ((ch + 1) * CHUNK_F4 <= n4) {
            #pragma unroll
            for (int i = 0; i < 4; i++) v[i] = __ldcs(&x4[bbase + i * NT]);
            #pragma unroll
            for (int i = 0; i < 4; i++) __stcs(&o4[bbase + i * NT], z4);
        } else {
            #pragma unroll
            for (int i = 0; i < 4; i++) {
                int idx = bbase + i * NT;
                if (idx < n4) { v[i] = __ldcs(&x4[idx]); __stcs(&o4[idx], z4); }
                else v[i] = make_float4(-1e30f, -1e30f, -1e30f, -1e30f);
            }
        }
        #pragma unroll
        for (int i = 0; i < 4; i++) {
            int i4 = bbase + i * NT;
            float vv[4] = {v[i].x, v[i].y, v[i].z, v[i].w};
            #pragma unroll
            for (int c = 0; c < 4; c++) {
                if (vv[c] >= gf) {
                    unsigned p = atomicAdd(&s_cnt, 1u);
                    unsigned key = fkey(vv[c]);
                    unsigned idx = ((unsigned)i4 << 2) + (unsigned)c;
                    if (p < SCAP) { u.st.key[p] = key; u.st.idx[p] = idx; }
                    else {
                        unsigned g = atomicAdd(&g_cand_cnt, 1u);
                        if (g < CANDCAP) { g_cand_key[g] = key; g_cand_idx[g] = idx; }
                    }
                }
            }
        }
    }
    // flush per-block staging once at end of the whole pass
    __syncthreads();
    {
        unsigned nloc = min(s_cnt, SCAP);
        if (nloc) {
            if (t == 0) s_gbase = atomicAdd(&g_cand_cnt, nloc);
            __syncthreads();
            for (unsigned i = t; i < nloc; i += NT) {
                unsigned g = s_gbase + i;
                if (g < CANDCAP) { g_cand_key[g] = u.st.key[i]; g_cand_idx[g] = u.st.idx[i]; }
            }
        }
    }
    grid_bar(base + 2 * NB);                                     // bar2

    const unsigned ncand = min(g_cand_cnt, CANDCAP);
    const unsigned cit = (ncand + NTHR - 1) / NTHR;

    // ---------------- Phase 2: top-12-bit histogram ----------------------
    for (int i = t; i < 4096; i += NT) u.hist[i] = 0;
    __syncthreads();
    for (unsigned s = 0; s < cit; s++) {
        unsigned j = gid + s * NTHR;
        bool v = j < ncand;
        unsigned bin = v ? (g_cand_key[j] >> 20) : 0u;
        wagg_add(u.hist, bin, v);
    }
    __syncthreads();
    for (int i = t; i < 4096; i += NT) {
        unsigned c = u.hist[i];
        if (c) atomicAdd(&g_histA[i], c);
    }
    for (unsigned i = gid; i < 4096; i += NTHR) g_hist_s[i] = 0;   // re-zero
    grid_bar(base + 3 * NB);                                     // bar3
    suffix_pick<16>(g_histA, K_TOTAL, s_scan, &s_bin, &s_rem);
    const unsigned b12 = s_bin, rank1 = s_rem;

    // ---------------- Phase 3: mid-12-bit histogram ----------------------
    for (int i = t; i < 4096; i += NT) u.hist[i] = 0;
    __syncthreads();
    for (unsigned s = 0; s < cit; s++) {
        unsigned j = gid + s * NTHR;
        bool v = j < ncand;
        unsigned key = v ? g_cand_key[j] : 0u;
        v = v && ((key >> 20) == b12);
        wagg_add(u.hist, (key >> 8) & 0xFFFu, v);
    }
    __syncthreads();
    for (int i = t; i < 4096; i += NT) {
        unsigned c = u.hist[i];
        if (c) atomicAdd(&g_histB[i], c);
    }
    grid_bar(base + 4 * NB);                                     // bar4
    suffix_pick<16>(g_histB, rank1, s_scan, &s_bin, &s_rem);
    const unsigned m12 = s_bin, rank2 = s_rem;
    const unsigned pref = (b12 << 12) | m12;

    // ---------------- Phase 4: low-8-bit histogram -----------------------
    if (t < 256) u.hist[t] = 0;
    __syncthreads();
    for (unsigned s = 0; s < cit; s++) {
        unsigned j = gid + s * NTHR;
        bool v = j < ncand;
        unsigned key = v ? g_cand_key[j] : 0u;
        v = v && ((key >> 8) == pref);
        wagg_add(u.hist, key & 0xFFu, v);
    }
    __syncthreads();
    {
        unsigned c = u.hist[t];
        if (c) atomicAdd(&g_hist8[t], c);
    }
    for (unsigned i = gid; i < 4096; i += NTHR) g_histA[i] = 0;    // re-zero
    grid_bar(base + 5 * NB);                                     // bar5
    suffix_pick<1>(g_hist8, rank2, s_scan, &s_bin, &s_rem);
    const unsigned lo8 = s_bin, need = s_rem;
    const unsigned count_eq = g_hist8[lo8];
    const unsigned ck = (pref << 8) | lo8;
    const bool ambig = (need != count_eq);
    const float rc = fmaxf(kval(ck), 0.f);

    // ---------------- Phase 5: winner scatter + EMA ----------------------
    for (unsigned s = 0; s < cit; s++) {
        unsigned j = gid + s * NTHR;
        if (j < ncand) {
            unsigned key = g_cand_key[j];
            if (key > ck) {
                out[g_cand_idx[j]] = fmaxf(kval(key), 0.f);
            } else if (key == ck) {
                if (!ambig) out[g_cand_idx[j]] = rc;
                else {
                    unsigned p = atomicAdd(&g_eq_cnt, 1u);
                    if (p < EQCAP) g_eq_idx[p] = g_cand_idx[j];
                }
            }
        }
    }
    if (gid == 0) out[ntot] = (1.0f - EMA_E) * thr[0] + EMA_E * rc;
    for (unsigned i = gid; i < 4096; i += NTHR) g_histB[i] = 0;    // re-zero
    grid_bar(base + 6 * NB);                                     // bar6

    // ---------------- Tail: re-zero state, tie fixup ---------------------
    if (gid < 256) g_hist8[gid] = 0;
    if (gid == 0) g_cand_cnt = 0;

    if (blockIdx.x == 0) {
        if (t == 0) g_base = base + 6 * NB;
        if (ambig) {
            // JAX tie-break: lowest flat index wins among equal-valued elems.
            unsigned ne = min(g_eq_cnt, EQCAP);
            __shared__ unsigned smin[256];
            __shared__ unsigned sbest;
            for (unsigned sel = 0; sel < need; sel++) {
                unsigned m = 0xFFFFFFFFu;
                for (unsigned j = t; j < ne; j += NT) m = min(m, g_eq_idx[j]);
                smin[t] = m;
                __syncthreads();
                for (int d = 128; d > 0; d >>= 1) {
                    if (t < d) smin[t] = min(smin[t], smin[t + d]);
                    __syncthreads();
                }
                if (t == 0) sbest = smin[0];
                __syncthreads();
                unsigned best = sbest;
                if (best == 0xFFFFFFFFu) break;
                for (unsigned j = t; j < ne; j += NT)
                    if (g_eq_idx[j] == best) g_eq_idx[j] = 0xFFFFFFFFu;
                if (t == 0) out[best] = rc;
                __syncthreads();
            }
        }
        if (t == 0) g_eq_cnt = 0;
    }
}

// ---------------------------------------------------------------------------
extern "C" void kernel_launch(void* const* d_in, const int* in_sizes, int n_in,
                              void* d_out, int out_size) {
    const float* x   = (const float*)d_in[0];
    const float* thr = (const float*)d_in[1];
    float* out = (float*)d_out;

    int n = in_sizes[0];
    int n4 = n / 4;
    int ntot = out_size - 1;   // threshold in last output slot

    k_all<<<NB, NT>>>(x, (const float4*)x, (float4*)out, thr, out, n, n4, ntot);
}

// round 5
// speedup vs baseline: 1.0678x; 1.0678x over previous
#include <cuda_runtime.h>
#include <cstdint>

// ---------------------------------------------------------------------------
// BatchTopK, two launches:
//   k_zero : one-shot pure-store pass (writes 100MB zeros) + fused sampled
//            12-bit histogram (first 96 blocks)
//   k_all  : persistent (592 blocks, 4 CTAs/SM):
//            guess pick -> pure-read candidate pass -> 3-level radix select
//            -> winner scatter + EMA threshold + tie fixup
// Global state re-zeroed at end for the next graph replay.
// ---------------------------------------------------------------------------

#define K_TOTAL       98304u       // 32 * 512 * 6
#define EMA_E         0.003f
#define CANDCAP       2097152u
#define EQCAP         4096u
#define SAMPLE_TARGET 1024u
#define NT            256
#define NB            592          // 148 SMs * 4 CTAs -> co-resident
#define NTHR          (NB * NT)    // 151552
#define NB_Z          3072
#define SCAP          2048u

static __device__ unsigned g_hist_s[4096];
static __device__ unsigned g_histA[4096];
static __device__ unsigned g_histB[4096];
static __device__ unsigned g_hist8[256];
static __device__ unsigned g_cand_key[CANDCAP];
static __device__ unsigned g_cand_idx[CANDCAP];
static __device__ unsigned g_eq_idx[EQCAP];
static __device__ unsigned g_cand_cnt;
static __device__ unsigned g_eq_cnt;
static __device__ unsigned g_bar;     // accumulating barrier counter
static __device__ unsigned g_base;    // barrier base (advances every run)

__device__ __forceinline__ unsigned fkey(float f) {
    unsigned u = __float_as_uint(f);
    return (u & 0x80000000u) ? ~u : (u | 0x80000000u);
}
__device__ __forceinline__ float kval(unsigned k) {
    unsigned u = (k & 0x80000000u) ? (k & 0x7FFFFFFFu) : ~k;
    return __uint_as_float(u);
}

__device__ __forceinline__ void grid_bar(unsigned target) {
    __syncthreads();
    if (threadIdx.x == 0) {
        __threadfence();
        atomicAdd(&g_bar, 1u);
        while (atomicAdd(&g_bar, 0u) < target) __nanosleep(64);
    }
    __syncthreads();
    __threadfence();
}

// Warp-aggregated shared-memory histogram add.
__device__ __forceinline__ void wagg_add(unsigned* sh, unsigned bin, bool valid) {
    unsigned lane = threadIdx.x & 31u;
    unsigned b = valid ? bin : (0x10000u + lane);
    unsigned m = __match_any_sync(0xFFFFFFFFu, b);
    if (valid && (unsigned)(__ffs(m) - 1) == lane)
        atomicAdd(&sh[bin], (unsigned)__popc(m));
}

// Block-redundant: suffix-scan 256*PER-bin histogram; max bin with suffix >= k.
template <int PER>
__device__ void suffix_pick(const unsigned* hist, unsigned k,
                            unsigned* s_scan, unsigned* s_bin, unsigned* s_rem) {
    int t = threadIdx.x;
    unsigned p = 0;
    #pragma unroll
    for (int i = 0; i < PER; i++) p += hist[t * PER + i];
    s_scan[t] = p;
    __syncthreads();
    for (int d = 1; d < 256; d <<= 1) {
        unsigned v = (t + d < 256) ? s_scan[t + d] : 0u;
        __syncthreads();
        s_scan[t] += v;
        __syncthreads();
    }
    if (s_scan[0] < k) {
        if (t == 0) { *s_bin = 0; *s_rem = 1; }
    } else {
        bool mine = (s_scan[t] >= k) && (t == 255 || s_scan[t + 1] < k);
        if (mine) {
            unsigned running = (t == 255) ? 0u : s_scan[t + 1];
            unsigned bsel = (unsigned)(t * PER);
            unsigned rem = 1;
            for (int i = PER - 1; i >= 0; i--) {
                unsigned h = hist[t * PER + i];
                if (running + h >= k) { bsel = (unsigned)(t * PER + i); rem = k - running; break; }
                running += h;
            }
            *s_bin = bsel; *s_rem = rem;
        }
    }
    __syncthreads();
}

// ---------------------------------------------------------------------------
// Launch 1: one-shot pure-store zeroing + sampled histogram in blocks 0..95.
__global__ void __launch_bounds__(NT) k_zero(const float* __restrict__ x,
                                             float4* __restrict__ o4,
                                             int n, int n4) {
    int base = blockIdx.x * (NT * 8) + threadIdx.x;
    const float4 z4 = make_float4(0.f, 0.f, 0.f, 0.f);
    #pragma unroll
    for (int i = 0; i < 8; i++) {
        int idx = base + i * NT;
        if (idx < n4) o4[idx] = z4;
    }
    if (blockIdx.x < 96) {
        __shared__ unsigned sh[4096];
        for (int i = threadIdx.x; i < 4096; i += NT) sh[i] = 0;
        __syncthreads();
        int nsamp = n >> 8;                           // sample every 256th
        #pragma unroll
        for (int s = 0; s < 4; s++) {
            int j = blockIdx.x * 1024 + s * NT + threadIdx.x;
            bool v = j < nsamp;
            unsigned bin = v ? (fkey(x[(size_t)j << 8]) >> 20) : 0u;
            wagg_add(sh, bin, v);
        }
        __syncthreads();
        for (int i = threadIdx.x; i < 4096; i += NT) {
            unsigned c = sh[i];
            if (c) atomicAdd(&g_hist_s[i], c);
        }
    }
}

// ---------------------------------------------------------------------------
// Launch 2: persistent. Pure-read candidate pass + exact select.
__global__ void __launch_bounds__(NT, 4)
k_all(const float4* __restrict__ x4, const float* __restrict__ thr,
      float* __restrict__ out, int n4, int ntot) {
    __shared__ union {
        unsigned hist[4096];
        struct { unsigned key[SCAP]; unsigned idx[SCAP]; } st;
    } u;
    __shared__ unsigned s_scan[256];
    __shared__ unsigned s_bin, s_rem, s_cnt, s_gbase;

    const int t = threadIdx.x;
    const unsigned gid = blockIdx.x * NT + t;
    const unsigned base = g_base;

    // ---- Phase A: pick guess from sampled histogram (kernel-boundary sync) ----
    suffix_pick<16>(g_hist_s, SAMPLE_TARGET, s_scan, &s_bin, &s_rem);
    const float gf = kval(s_bin << 20);

    // ---- Phase 1: pure-read pass, collect candidates >= gf ----
    if (t == 0) s_cnt = 0;
    __syncthreads();
    for (unsigned b = gid; b < (unsigned)n4; b += 8u * NTHR) {
        float4 v[8];
        #pragma unroll
        for (int k = 0; k < 8; k++) {
            unsigned idx = b + (unsigned)k * NTHR;
            v[k] = (idx < (unsigned)n4) ? __ldcs(&x4[idx])
                                        : make_float4(-1e30f, -1e30f, -1e30f, -1e30f);
        }
        #pragma unroll
        for (int k = 0; k < 8; k++) {
            unsigned idx = b + (unsigned)k * NTHR;
            float vv[4] = {v[k].x, v[k].y, v[k].z, v[k].w};
            #pragma unroll
            for (int c = 0; c < 4; c++) {
                if (vv[c] >= gf) {
                    unsigned p = atomicAdd(&s_cnt, 1u);
                    unsigned key = fkey(vv[c]);
                    unsigned fid = (idx << 2) + (unsigned)c;
                    if (p < SCAP) { u.st.key[p] = key; u.st.idx[p] = fid; }
                    else {
                        unsigned g = atomicAdd(&g_cand_cnt, 1u);
                        if (g < CANDCAP) { g_cand_key[g] = key; g_cand_idx[g] = fid; }
                    }
                }
            }
        }
    }
    __syncthreads();
    {
        unsigned nloc = min(s_cnt, SCAP);
        if (nloc) {
            if (t == 0) s_gbase = atomicAdd(&g_cand_cnt, nloc);
            __syncthreads();
            for (unsigned i = t; i < nloc; i += NT) {
                unsigned g = s_gbase + i;
                if (g < CANDCAP) { g_cand_key[g] = u.st.key[i]; g_cand_idx[g] = u.st.idx[i]; }
            }
        }
    }
    grid_bar(base + NB);                                         // bar1

    const unsigned ncand = min(g_cand_cnt, CANDCAP);
    const unsigned cit = (ncand + NTHR - 1) / NTHR;

    // ---- Phase 2: top-12-bit histogram ----
    for (int i = t; i < 4096; i += NT) u.hist[i] = 0;
    __syncthreads();
    for (unsigned s = 0; s < cit; s++) {
        unsigned j = gid + s * NTHR;
        bool v = j < ncand;
        unsigned bin = v ? (g_cand_key[j] >> 20) : 0u;
        wagg_add(u.hist, bin, v);
    }
    __syncthreads();
    for (int i = t; i < 4096; i += NT) {
        unsigned c = u.hist[i];
        if (c) atomicAdd(&g_histA[i], c);
    }
    for (unsigned i = gid; i < 4096; i += NTHR) g_hist_s[i] = 0;   // re-zero
    grid_bar(base + 2 * NB);                                     // bar2
    suffix_pick<16>(g_histA, K_TOTAL, s_scan, &s_bin, &s_rem);
    const unsigned b12 = s_bin, rank1 = s_rem;

    // ---- Phase 3: mid-12-bit histogram ----
    for (int i = t; i < 4096; i += NT) u.hist[i] = 0;
    __syncthreads();
    for (unsigned s = 0; s < cit; s++) {
        unsigned j = gid + s * NTHR;
        bool v = j < ncand;
        unsigned key = v ? g_cand_key[j] : 0u;
        v = v && ((key >> 20) == b12);
        wagg_add(u.hist, (key >> 8) & 0xFFFu, v);
    }
    __syncthreads();
    for (int i = t; i < 4096; i += NT) {
        unsigned c = u.hist[i];
        if (c) atomicAdd(&g_histB[i], c);
    }
    grid_bar(base + 3 * NB);                                     // bar3
    suffix_pick<16>(g_histB, rank1, s_scan, &s_bin, &s_rem);
    const unsigned m12 = s_bin, rank2 = s_rem;
    const unsigned pref = (b12 << 12) | m12;

    // ---- Phase 4: low-8-bit histogram ----
    if (t < 256) u.hist[t] = 0;
    __syncthreads();
    for (unsigned s = 0; s < cit; s++) {
        unsigned j = gid + s * NTHR;
        bool v = j < ncand;
        unsigned key = v ? g_cand_key[j] : 0u;
        v = v && ((key >> 8) == pref);
        wagg_add(u.hist, key & 0xFFu, v);
    }
    __syncthreads();
    {
        unsigned c = u.hist[t];
        if (c) atomicAdd(&g_hist8[t], c);
    }
    for (unsigned i = gid; i < 4096; i += NTHR) g_histA[i] = 0;    // re-zero
    grid_bar(base + 4 * NB);                                     // bar4
    suffix_pick<1>(g_hist8, rank2, s_scan, &s_bin, &s_rem);
    const unsigned lo8 = s_bin, need = s_rem;
    const unsigned count_eq = g_hist8[lo8];
    const unsigned ck = (pref << 8) | lo8;
    const bool ambig = (need != count_eq);
    const float rc = fmaxf(kval(ck), 0.f);

    // ---- Phase 5: winner scatter + EMA ----
    for (unsigned s = 0; s < cit; s++) {
        unsigned j = gid + s * NTHR;
        if (j < ncand) {
            unsigned key = g_cand_key[j];
            if (key > ck) {
                out[g_cand_idx[j]] = fmaxf(kval(key), 0.f);
            } else if (key == ck) {
                if (!ambig) out[g_cand_idx[j]] = rc;
                else {
                    unsigned p = atomicAdd(&g_eq_cnt, 1u);
                    if (p < EQCAP) g_eq_idx[p] = g_cand_idx[j];
                }
            }
        }
    }
    if (gid == 0) out[ntot] = (1.0f - EMA_E) * thr[0] + EMA_E * rc;
    for (unsigned i = gid; i < 4096; i += NTHR) g_histB[i] = 0;    // re-zero
    grid_bar(base + 5 * NB);                                     // bar5

    // ---- Tail: re-zero state, tie fixup ----
    if (gid < 256) g_hist8[gid] = 0;
    if (gid == 0) g_cand_cnt = 0;

    if (blockIdx.x == 0) {
        if (t == 0) g_base = base + 5 * NB;
        if (ambig) {
            // JAX tie-break: lowest flat index wins among equal-valued elems.
            unsigned ne = min(g_eq_cnt, EQCAP);
            __shared__ unsigned smin[256];
            __shared__ unsigned sbest;
            for (unsigned sel = 0; sel < need; sel++) {
                unsigned m = 0xFFFFFFFFu;
                for (unsigned j = t; j < ne; j += NT) m = min(m, g_eq_idx[j]);
                smin[t] = m;
                __syncthreads();
                for (int d = 128; d > 0; d >>= 1) {
                    if (t < d) smin[t] = min(smin[t], smin[t + d]);
                    __syncthreads();
                }
                if (t == 0) sbest = smin[0];
                __syncthreads();
                unsigned best = sbest;
                if (best == 0xFFFFFFFFu) break;
                for (unsigned j = t; j < ne; j += NT)
                    if (g_eq_idx[j] == best) g_eq_idx[j] = 0xFFFFFFFFu;
                if (t == 0) out[best] = rc;
                __syncthreads();
            }
        }
        if (t == 0) g_eq_cnt = 0;
    }
}

// ---------------------------------------------------------------------------
extern "C" void kernel_launch(void* const* d_in, const int* in_sizes, int n_in,
                              void* d_out, int out_size) {
    const float* x   = (const float*)d_in[0];
    const float* thr = (const float*)d_in[1];
    float* out = (float*)d_out;

    int n = in_sizes[0];
    int n4 = n / 4;
    int ntot = out_size - 1;   // threshold in last output slot

    k_zero<<<NB_Z, NT>>>(x, (float4*)out, n, n4);
    k_all<<<NB, NT>>>((const float4*)x, thr, out, n4, ntot);
}

// round 6
// speedup vs baseline: 1.1358x; 1.0637x over previous
#include <cuda_runtime.h>
#include <cstdint>

// ---------------------------------------------------------------------------
// BatchTopK, three launches (streaming = one-shot grids; select = persistent):
//   k_sample : one-shot, sampled 12-bit hist; last-finisher block picks guess
//   k_main   : one-shot full read+write pass (zeros out, collects candidates)
//   k_select : persistent 148 blocks: 3-level radix select + scatter + ties
// ---------------------------------------------------------------------------

#define K_TOTAL       98304u       // 32 * 512 * 6
#define EMA_E         0.003f
#define CANDCAP       2097152u
#define EQCAP         4096u
#define SAMPLE_TARGET 1024u
#define NT            256
#define NBS           384          // sample blocks (98304 samples, 1/thread)
#define NB_SEL        148          // 1 CTA/SM -> co-resident trivially
#define NTHR_SEL      (NB_SEL * NT)
#define CHUNK_F4      2048         // 256 threads * 8 float4
#define SCAP          1024u

static __device__ unsigned g_hist_s[4096];
static __device__ unsigned g_histA[4096];
static __device__ unsigned g_histB[4096];
static __device__ unsigned g_hist8[256];
static __device__ unsigned g_cand_key[CANDCAP];
static __device__ unsigned g_cand_idx[CANDCAP];
static __device__ unsigned g_eq_idx[EQCAP];
static __device__ unsigned g_cand_cnt;
static __device__ unsigned g_eq_cnt;
static __device__ unsigned g_tick;      // last-finisher ticket for k_sample
static __device__ float    g_gf;        // guess threshold (float domain)
static __device__ unsigned g_bar;       // accumulating barrier counter
static __device__ unsigned g_base;      // barrier base (advances every run)

__device__ __forceinline__ unsigned fkey(float f) {
    unsigned u = __float_as_uint(f);
    return (u & 0x80000000u) ? ~u : (u | 0x80000000u);
}
__device__ __forceinline__ float kval(unsigned k) {
    unsigned u = (k & 0x80000000u) ? (k & 0x7FFFFFFFu) : ~k;
    return __uint_as_float(u);
}

__device__ __forceinline__ void grid_bar(unsigned target) {
    __syncthreads();
    if (threadIdx.x == 0) {
        __threadfence();
        atomicAdd(&g_bar, 1u);
        while (atomicAdd(&g_bar, 0u) < target) __nanosleep(32);
    }
    __syncthreads();
    __threadfence();
}

// Warp-aggregated shared-memory histogram add.
__device__ __forceinline__ void wagg_add(unsigned* sh, unsigned bin, bool valid) {
    unsigned lane = threadIdx.x & 31u;
    unsigned b = valid ? bin : (0x10000u + lane);
    unsigned m = __match_any_sync(0xFFFFFFFFu, b);
    if (valid && (unsigned)(__ffs(m) - 1) == lane)
        atomicAdd(&sh[bin], (unsigned)__popc(m));
}

// Block-wide: suffix-scan 256*PER-bin histogram; max bin with suffix >= k.
template <int PER>
__device__ void suffix_pick(const unsigned* hist, unsigned k,
                            unsigned* s_scan, unsigned* s_bin, unsigned* s_rem) {
    int t = threadIdx.x;
    unsigned p = 0;
    #pragma unroll
    for (int i = 0; i < PER; i++) p += hist[t * PER + i];
    s_scan[t] = p;
    __syncthreads();
    for (int d = 1; d < 256; d <<= 1) {
        unsigned v = (t + d < 256) ? s_scan[t + d] : 0u;
        __syncthreads();
        s_scan[t] += v;
        __syncthreads();
    }
    if (s_scan[0] < k) {
        if (t == 0) { *s_bin = 0; *s_rem = 1; }
    } else {
        bool mine = (s_scan[t] >= k) && (t == 255 || s_scan[t + 1] < k);
        if (mine) {
            unsigned running = (t == 255) ? 0u : s_scan[t + 1];
            unsigned bsel = (unsigned)(t * PER);
            unsigned rem = 1;
            for (int i = PER - 1; i >= 0; i--) {
                unsigned h = hist[t * PER + i];
                if (running + h >= k) { bsel = (unsigned)(t * PER + i); rem = k - running; break; }
                running += h;
            }
            *s_bin = bsel; *s_rem = rem;
        }
    }
    __syncthreads();
}

// ---------------------------------------------------------------------------
// Launch 1: sampled histogram; last-finisher block computes the guess.
__global__ void __launch_bounds__(NT) k_sample(const float* __restrict__ x, int n) {
    __shared__ unsigned sh[4096];
    __shared__ unsigned s_scan[256];
    __shared__ unsigned s_bin, s_rem;
    __shared__ bool s_last;
    const int t = threadIdx.x;

    for (int i = t; i < 4096; i += NT) sh[i] = 0;
    __syncthreads();
    int nsamp = n >> 8;                              // every 256th element
    int j = blockIdx.x * NT + t;
    bool v = j < nsamp;
    unsigned bin = v ? (fkey(x[(size_t)j << 8]) >> 20) : 0u;
    wagg_add(sh, bin, v);
    __syncthreads();
    for (int i = t; i < 4096; i += NT) {
        unsigned c = sh[i];
        if (c) atomicAdd(&g_hist_s[i], c);
    }
    // last-finisher election
    __threadfence();
    __syncthreads();
    if (t == 0) {
        unsigned old = atomicAdd(&g_tick, 1u);
        s_last = (old == NBS - 1);
    }
    __syncthreads();
    if (s_last) {
        __threadfence();
        suffix_pick<16>(g_hist_s, SAMPLE_TARGET, s_scan, &s_bin, &s_rem);
        if (t == 0) {
            g_gf = kval(s_bin << 20);
            g_cand_cnt = 0;
            g_eq_cnt = 0;
            g_tick = 0;
        }
        for (int i = t; i < 4096; i += NT) g_hist_s[i] = 0;   // ready for next replay
        __threadfence();
    }
}

// ---------------------------------------------------------------------------
// Launch 2: the full pass (one-shot). Zero output, collect candidates >= gf.
__global__ void __launch_bounds__(NT) k_main(const float4* __restrict__ x4,
                                             float4* __restrict__ o4, int n4) {
    __shared__ unsigned s_key[SCAP];
    __shared__ unsigned s_idx[SCAP];
    __shared__ unsigned s_cnt, s_base;
    if (threadIdx.x == 0) s_cnt = 0;
    __syncthreads();

    const float gf = g_gf;
    int base = blockIdx.x * CHUNK_F4 + threadIdx.x;
    float4 v[8];
    const float4 z4 = make_float4(0.f, 0.f, 0.f, 0.f);

    if ((blockIdx.x + 1) * CHUNK_F4 <= n4) {
        #pragma unroll
        for (int it = 0; it < 8; it++) v[it] = x4[base + it * NT];
        #pragma unroll
        for (int it = 0; it < 8; it++) o4[base + it * NT] = z4;
    } else {
        #pragma unroll
        for (int it = 0; it < 8; it++) {
            int i = base + it * NT;
            if (i < n4) { v[it] = x4[i]; o4[i] = z4; }
            else v[it] = make_float4(-1e30f, -1e30f, -1e30f, -1e30f);
        }
    }

    #pragma unroll
    for (int it = 0; it < 8; it++) {
        int i4 = base + it * NT;
        float vv[4] = {v[it].x, v[it].y, v[it].z, v[it].w};
        #pragma unroll
        for (int c = 0; c < 4; c++) {
            if (vv[c] >= gf) {
                unsigned p = atomicAdd(&s_cnt, 1u);
                unsigned key = fkey(vv[c]);
                unsigned idx = ((unsigned)i4 << 2) + (unsigned)c;
                if (p < SCAP) { s_key[p] = key; s_idx[p] = idx; }
                else {
                    unsigned g = atomicAdd(&g_cand_cnt, 1u);
                    if (g < CANDCAP) { g_cand_key[g] = key; g_cand_idx[g] = idx; }
                }
            }
        }
    }
    __syncthreads();
    unsigned nloc = min(s_cnt, SCAP);
    if (threadIdx.x == 0) s_base = atomicAdd(&g_cand_cnt, nloc);
    __syncthreads();
    for (unsigned i = threadIdx.x; i < nloc; i += NT) {
        unsigned g = s_base + i;
        if (g < CANDCAP) { g_cand_key[g] = s_key[i]; g_cand_idx[g] = s_idx[i]; }
    }
}

// ---------------------------------------------------------------------------
// Launch 3: persistent select (148 blocks, 1/SM).
__global__ void __launch_bounds__(NT)
k_select(const float* __restrict__ thr, float* __restrict__ out, int ntot) {
    __shared__ unsigned sh[4096];
    __shared__ unsigned s_scan[256];
    __shared__ unsigned s_bin, s_rem;
    const int t = threadIdx.x;
    const unsigned gid = blockIdx.x * NT + t;
    const unsigned base = g_base;

    const unsigned ncand = min(g_cand_cnt, CANDCAP);
    const unsigned cit = (ncand + NTHR_SEL - 1) / NTHR_SEL;

    // ---- Phase 2: top-12-bit histogram ----
    for (int i = t; i < 4096; i += NT) sh[i] = 0;
    __syncthreads();
    for (unsigned s = 0; s < cit; s++) {
        unsigned j = gid + s * NTHR_SEL;
        bool v = j < ncand;
        unsigned bin = v ? (g_cand_key[j] >> 20) : 0u;
        wagg_add(sh, bin, v);
    }
    __syncthreads();
    for (int i = t; i < 4096; i += NT) {
        unsigned c = sh[i];
        if (c) atomicAdd(&g_histA[i], c);
    }
    grid_bar(base + NB_SEL);                                  // bar1
    suffix_pick<16>(g_histA, K_TOTAL, s_scan, &s_bin, &s_rem);
    const unsigned b12 = s_bin, rank1 = s_rem;

    // ---- Phase 3: mid-12-bit histogram (within b12) ----
    for (int i = t; i < 4096; i += NT) sh[i] = 0;
    __syncthreads();
    for (unsigned s = 0; s < cit; s++) {
        unsigned j = gid + s * NTHR_SEL;
        bool v = j < ncand;
        unsigned key = v ? g_cand_key[j] : 0u;
        v = v && ((key >> 20) == b12);
        wagg_add(sh, (key >> 8) & 0xFFFu, v);
    }
    __syncthreads();
    for (int i = t; i < 4096; i += NT) {
        unsigned c = sh[i];
        if (c) atomicAdd(&g_histB[i], c);
    }
    grid_bar(base + 2 * NB_SEL);                              // bar2
    suffix_pick<16>(g_histB, rank1, s_scan, &s_bin, &s_rem);
    const unsigned m12 = s_bin, rank2 = s_rem;
    const unsigned pref = (b12 << 12) | m12;

    // ---- Phase 4: low-8-bit histogram (within pref); also re-zero histA ----
    if (t < 256) sh[t] = 0;
    __syncthreads();
    for (unsigned s = 0; s < cit; s++) {
        unsigned j = gid + s * NTHR_SEL;
        bool v = j < ncand;
        unsigned key = v ? g_cand_key[j] : 0u;
        v = v && ((key >> 8) == pref);
        wagg_add(sh, key & 0xFFu, v);
    }
    __syncthreads();
    {
        unsigned c = sh[t];
        if (c) atomicAdd(&g_hist8[t], c);
    }
    for (unsigned i = gid; i < 4096; i += NTHR_SEL) g_histA[i] = 0;
    grid_bar(base + 3 * NB_SEL);                              // bar3
    suffix_pick<1>(g_hist8, rank2, s_scan, &s_bin, &s_rem);
    const unsigned lo8 = s_bin, need = s_rem;
    const unsigned count_eq = g_hist8[lo8];
    const unsigned ck = (pref << 8) | lo8;
    const bool ambig = (need != count_eq);
    const float rc = fmaxf(kval(ck), 0.f);

    // ---- Phase 5: winner scatter + EMA ----
    for (unsigned s = 0; s < cit; s++) {
        unsigned j = gid + s * NTHR_SEL;
        if (j < ncand) {
            unsigned key = g_cand_key[j];
            if (key > ck) {
                out[g_cand_idx[j]] = fmaxf(kval(key), 0.f);
            } else if (key == ck) {
                if (!ambig) out[g_cand_idx[j]] = rc;
                else {
                    unsigned p = atomicAdd(&g_eq_cnt, 1u);
                    if (p < EQCAP) g_eq_idx[p] = g_cand_idx[j];
                }
            }
        }
    }
    if (gid == 0) out[ntot] = (1.0f - EMA_E) * thr[0] + EMA_E * rc;
    grid_bar(base + 4 * NB_SEL);                              // bar4

    // ---- Tail: re-zero used state, tie fixup in block 0 ----
    for (unsigned i = gid; i < 4096; i += NTHR_SEL) g_histB[i] = 0;
    if (gid < 256) g_hist8[gid] = 0;

    if (blockIdx.x == 0) {
        if (t == 0) g_base = base + 4 * NB_SEL;
        if (ambig) {
            // JAX tie-break: lowest flat index wins among equal-valued elems.
            unsigned ne = min(g_eq_cnt, EQCAP);
            __shared__ unsigned smin[256];
            __shared__ unsigned sbest;
            for (unsigned sel = 0; sel < need; sel++) {
                unsigned m = 0xFFFFFFFFu;
                for (unsigned j = t; j < ne; j += NT) m = min(m, g_eq_idx[j]);
                smin[t] = m;
                __syncthreads();
                for (int d = 128; d > 0; d >>= 1) {
                    if (t < d) smin[t] = min(smin[t], smin[t + d]);
                    __syncthreads();
                }
                if (t == 0) sbest = smin[0];
                __syncthreads();
                unsigned best = sbest;
                if (best == 0xFFFFFFFFu) break;
                for (unsigned j = t; j < ne; j += NT)
                    if (g_eq_idx[j] == best) g_eq_idx[j] = 0xFFFFFFFFu;
                if (t == 0) out[best] = rc;
                __syncthreads();
            }
        }
    }
}

// ---------------------------------------------------------------------------
extern "C" void kernel_launch(void* const* d_in, const int* in_sizes, int n_in,
                              void* d_out, int out_size) {
    const float* x   = (const float*)d_in[0];
    const float* thr = (const float*)d_in[1];
    float* out = (float*)d_out;

    int n = in_sizes[0];
    int n4 = n / 4;
    int ntot = out_size - 1;   // threshold in last output slot

    k_sample<<<NBS, NT>>>(x, n);

    int nchunks = (n4 + CHUNK_F4 - 1) / CHUNK_F4;
    k_main<<<nchunks, NT>>>((const float4*)x, (float4*)out, n4);

    k_select<<<NB_SEL, NT>>>(thr, out, ntot);
}

// round 7
// speedup vs baseline: 1.1582x; 1.0197x over previous
#include <cuda_runtime.h>
#include <cstdint>

// ---------------------------------------------------------------------------
// BatchTopK, three launches:
//   k_sample : coalesced chunk sampling -> 12-bit hist -> guess (last finisher)
//   k_main   : one-shot full read+write pass (zeros out, collects candidates)
//   k_select : persistent 148 blocks: hist -> scatter+compact -> finish on the
//              ~36k cutoff-bin side buffer. 3 barriers (+1 if ambiguous ties).
// ---------------------------------------------------------------------------

#define K_TOTAL       98304u       // 32 * 512 * 6
#define EMA_E         0.003f
#define CANDCAP       2097152u
#define SIDECAP       262144u
#define EQCAP         4096u
#define SAMPLE_TARGET 1024u
#define NT            256
#define NBS           96           // sample blocks: 96*8 warps * 128 floats
#define NB_SEL        148          // 1 CTA/SM
#define NTHR_SEL      (NB_SEL * NT)
#define CHUNK_F4      2048         // k_main: 256 threads * 8 float4
#define SCAP          1024u

static __device__ unsigned g_hist_s[4096];
static __device__ unsigned g_histA[4096];
static __device__ unsigned g_histB[4096];
static __device__ unsigned g_hist8[256];
static __device__ unsigned g_cand_key[CANDCAP];
static __device__ unsigned g_cand_idx[CANDCAP];
static __device__ unsigned g_side_key[SIDECAP];
static __device__ unsigned g_side_idx[SIDECAP];
static __device__ unsigned g_eq_idx[EQCAP];
static __device__ unsigned g_cand_cnt;
static __device__ unsigned g_side_cnt;
static __device__ unsigned g_eq_cnt;
static __device__ unsigned g_tick;      // last-finisher ticket for k_sample
static __device__ float    g_gf;        // guess threshold (float domain)
static __device__ unsigned g_bar;       // accumulating barrier counter
static __device__ unsigned g_base;      // barrier base (advances every run)

__device__ __forceinline__ unsigned fkey(float f) {
    unsigned u = __float_as_uint(f);
    return (u & 0x80000000u) ? ~u : (u | 0x80000000u);
}
__device__ __forceinline__ float kval(unsigned k) {
    unsigned u = (k & 0x80000000u) ? (k & 0x7FFFFFFFu) : ~k;
    return __uint_as_float(u);
}

__device__ __forceinline__ void grid_bar(unsigned target) {
    __syncthreads();
    if (threadIdx.x == 0) {
        __threadfence();
        atomicAdd(&g_bar, 1u);
        while (atomicAdd(&g_bar, 0u) < target) __nanosleep(32);
    }
    __syncthreads();
    __threadfence();
}

// Warp-aggregated shared-memory histogram add.
__device__ __forceinline__ void wagg_add(unsigned* sh, unsigned bin, bool valid) {
    unsigned lane = threadIdx.x & 31u;
    unsigned b = valid ? bin : (0x10000u + lane);
    unsigned m = __match_any_sync(0xFFFFFFFFu, b);
    if (valid && (unsigned)(__ffs(m) - 1) == lane)
        atomicAdd(&sh[bin], (unsigned)__popc(m));
}

// Warp-aggregated global append: returns slot for this lane (valid lanes only).
__device__ __forceinline__ unsigned wagg_append(unsigned* cnt, bool valid) {
    unsigned mask = __ballot_sync(0xFFFFFFFFu, valid);
    unsigned lane = threadIdx.x & 31u;
    unsigned leader = __ffs(mask) - 1u;
    unsigned base = 0;
    if (lane == leader) base = atomicAdd(cnt, (unsigned)__popc(mask));
    base = __shfl_sync(0xFFFFFFFFu, base, leader);
    return base + (unsigned)__popc(mask & ((1u << lane) - 1u));
}

// Block-wide: suffix-scan 256*PER-bin histogram; max bin with suffix >= k.
template <int PER>
__device__ void suffix_pick(const unsigned* hist, unsigned k,
                            unsigned* s_scan, unsigned* s_bin, unsigned* s_rem) {
    int t = threadIdx.x;
    unsigned p = 0;
    #pragma unroll
    for (int i = 0; i < PER; i++) p += hist[t * PER + i];
    s_scan[t] = p;
    __syncthreads();
    for (int d = 1; d < 256; d <<= 1) {
        unsigned v = (t + d < 256) ? s_scan[t + d] : 0u;
        __syncthreads();
        s_scan[t] += v;
        __syncthreads();
    }
    if (s_scan[0] < k) {
        if (t == 0) { *s_bin = 0; *s_rem = 1; }
    } else {
        bool mine = (s_scan[t] >= k) && (t == 255 || s_scan[t + 1] < k);
        if (mine) {
            unsigned running = (t == 255) ? 0u : s_scan[t + 1];
            unsigned bsel = (unsigned)(t * PER);
            unsigned rem = 1;
            for (int i = PER - 1; i >= 0; i--) {
                unsigned h = hist[t * PER + i];
                if (running + h >= k) { bsel = (unsigned)(t * PER + i); rem = k - running; break; }
                running += h;
            }
            *s_bin = bsel; *s_rem = rem;
        }
    }
    __syncthreads();
}

// ---------------------------------------------------------------------------
// Launch 1: coalesced chunk sampling (iid data -> contiguous chunks are a
// valid sample). 768 warps, each reads 32 consecutive float4 (512B) at an
// evenly spaced offset. Last-finisher block picks the guess + resets state.
__global__ void __launch_bounds__(NT) k_sample(const float4* __restrict__ x4, int n4) {
    __shared__ unsigned sh[4096];
    __shared__ unsigned s_scan[256];
    __shared__ unsigned s_bin, s_rem;
    __shared__ bool s_last;
    const int t = threadIdx.x;

    for (int i = t; i < 4096; i += NT) sh[i] = 0;
    __syncthreads();

    const int warp = blockIdx.x * 8 + (t >> 5);     // 0..767
    const int lane = t & 31;
    const int nwarp = NBS * 8;                      // 768 chunks
    long long pos = (long long)warp * (n4 / nwarp) + lane;
    float4 v = x4[pos];
    wagg_add(sh, fkey(v.x) >> 20, true);
    wagg_add(sh, fkey(v.y) >> 20, true);
    wagg_add(sh, fkey(v.z) >> 20, true);
    wagg_add(sh, fkey(v.w) >> 20, true);
    __syncthreads();
    for (int i = t; i < 4096; i += NT) {
        unsigned c = sh[i];
        if (c) atomicAdd(&g_hist_s[i], c);
    }
    __threadfence();
    __syncthreads();
    if (t == 0) {
        unsigned old = atomicAdd(&g_tick, 1u);
        s_last = (old == NBS - 1);
    }
    __syncthreads();
    if (s_last) {
        __threadfence();
        suffix_pick<16>(g_hist_s, SAMPLE_TARGET, s_scan, &s_bin, &s_rem);
        if (t == 0) {
            g_gf = kval(s_bin << 20);
            g_cand_cnt = 0;
            g_side_cnt = 0;
            g_eq_cnt = 0;
            g_tick = 0;
        }
        for (int i = t; i < 4096; i += NT) g_hist_s[i] = 0;
        __threadfence();
    }
}

// ---------------------------------------------------------------------------
// Launch 2: the full pass (one-shot). Zero output, collect candidates >= gf.
__global__ void __launch_bounds__(NT) k_main(const float4* __restrict__ x4,
                                             float4* __restrict__ o4, int n4) {
    __shared__ unsigned s_key[SCAP];
    __shared__ unsigned s_idx[SCAP];
    __shared__ unsigned s_cnt, s_base;
    if (threadIdx.x == 0) s_cnt = 0;
    __syncthreads();

    const float gf = g_gf;
    int base = blockIdx.x * CHUNK_F4 + threadIdx.x;
    float4 v[8];
    const float4 z4 = make_float4(0.f, 0.f, 0.f, 0.f);

    if ((blockIdx.x + 1) * CHUNK_F4 <= n4) {
        #pragma unroll
        for (int it = 0; it < 8; it++) v[it] = x4[base + it * NT];
        #pragma unroll
        for (int it = 0; it < 8; it++) o4[base + it * NT] = z4;
    } else {
        #pragma unroll
        for (int it = 0; it < 8; it++) {
            int i = base + it * NT;
            if (i < n4) { v[it] = x4[i]; o4[i] = z4; }
            else v[it] = make_float4(-1e30f, -1e30f, -1e30f, -1e30f);
        }
    }

    #pragma unroll
    for (int it = 0; it < 8; it++) {
        int i4 = base + it * NT;
        float vv[4] = {v[it].x, v[it].y, v[it].z, v[it].w};
        #pragma unroll
        for (int c = 0; c < 4; c++) {
            if (vv[c] >= gf) {
                unsigned p = atomicAdd(&s_cnt, 1u);
                unsigned key = fkey(vv[c]);
                unsigned idx = ((unsigned)i4 << 2) + (unsigned)c;
                if (p < SCAP) { s_key[p] = key; s_idx[p] = idx; }
                else {
                    unsigned g = atomicAdd(&g_cand_cnt, 1u);
                    if (g < CANDCAP) { g_cand_key[g] = key; g_cand_idx[g] = idx; }
                }
            }
        }
    }
    __syncthreads();
    unsigned nloc = min(s_cnt, SCAP);
    if (threadIdx.x == 0) s_base = atomicAdd(&g_cand_cnt, nloc);
    __syncthreads();
    for (unsigned i = threadIdx.x; i < nloc; i += NT) {
        unsigned g = s_base + i;
        if (g < CANDCAP) { g_cand_key[g] = s_key[i]; g_cand_idx[g] = s_idx[i]; }
    }
}

// ---------------------------------------------------------------------------
// Launch 3: persistent select (148 blocks).
__global__ void __launch_bounds__(NT)
k_select(const float* __restrict__ thr, float* __restrict__ out, int ntot) {
    __shared__ unsigned sh[4096];
    __shared__ unsigned s_scan[256];
    __shared__ unsigned s_bin, s_rem;
    const int t = threadIdx.x;
    const unsigned gid = blockIdx.x * NT + t;
    const unsigned base = g_base;

    const unsigned ncand = min(g_cand_cnt, CANDCAP);
    const unsigned cit = (ncand + NTHR_SEL - 1) / NTHR_SEL;

    // ---- Pass 1 over candidates: top-12-bit histogram ----
    for (int i = t; i < 4096; i += NT) sh[i] = 0;
    __syncthreads();
    for (unsigned s = 0; s < cit; s++) {
        unsigned j = gid + s * NTHR_SEL;
        bool v = j < ncand;
        unsigned bin = v ? (g_cand_key[j] >> 20) : 0u;
        wagg_add(sh, bin, v);
    }
    __syncthreads();
    for (int i = t; i < 4096; i += NT) {
        unsigned c = sh[i];
        if (c) atomicAdd(&g_histA[i], c);
    }
    grid_bar(base + NB_SEL);                                  // bar1
    suffix_pick<16>(g_histA, K_TOTAL, s_scan, &s_bin, &s_rem);
    const unsigned b12 = s_bin, rank1 = s_rem;

    // ---- Pass 2 over candidates: scatter decided winners (top12 > b12),
    //      compact cutoff-bin entries to side buffer, build mid-12 hist ----
    for (int i = t; i < 4096; i += NT) sh[i] = 0;
    __syncthreads();
    for (unsigned s = 0; s < cit; s++) {
        unsigned j = gid + s * NTHR_SEL;
        bool v = j < ncand;
        unsigned key = v ? g_cand_key[j] : 0u;
        unsigned top = key >> 20;
        if (v && top > b12)
            out[g_cand_idx[j]] = fmaxf(kval(key), 0.f);
        bool inbin = v && (top == b12);
        unsigned slot = wagg_append(&g_side_cnt, inbin);
        if (inbin && slot < SIDECAP) {
            g_side_key[slot] = key;
            g_side_idx[slot] = g_cand_idx[j];
        }
        wagg_add(sh, (key >> 8) & 0xFFFu, inbin);
    }
    __syncthreads();
    for (int i = t; i < 4096; i += NT) {
        unsigned c = sh[i];
        if (c) atomicAdd(&g_histB[i], c);
    }
    for (unsigned i = gid; i < 4096; i += NTHR_SEL) g_histA[i] = 0;   // re-zero
    grid_bar(base + 2 * NB_SEL);                              // bar2
    suffix_pick<16>(g_histB, rank1, s_scan, &s_bin, &s_rem);
    const unsigned m12 = s_bin, rank2 = s_rem;

    const unsigned ns = min(g_side_cnt, SIDECAP);
    const unsigned sit = (ns + NTHR_SEL - 1) / NTHR_SEL;

    // ---- Pass over side buffer: scatter mid12 > m12 winners, low-8 hist ----
    if (t < 256) sh[t] = 0;
    __syncthreads();
    for (unsigned s = 0; s < sit; s++) {
        unsigned j = gid + s * NTHR_SEL;
        bool v = j < ns;
        unsigned key = v ? g_side_key[j] : 0u;
        unsigned mid = (key >> 8) & 0xFFFu;
        if (v && mid > m12)
            out[g_side_idx[j]] = fmaxf(kval(key), 0.f);
        wagg_add(sh, key & 0xFFu, v && (mid == m12));
    }
    __syncthreads();
    {
        unsigned c = sh[t];
        if (c) atomicAdd(&g_hist8[t], c);
    }
    for (unsigned i = gid; i < 4096; i += NTHR_SEL) g_histB[i] = 0;   // re-zero
    grid_bar(base + 3 * NB_SEL);                              // bar3
    suffix_pick<1>(g_hist8, rank2, s_scan, &s_bin, &s_rem);
    const unsigned lo8 = s_bin, need = s_rem;
    const unsigned count_eq = g_hist8[lo8];
    const bool ambig = (need != count_eq);
    const unsigned ck = (b12 << 20) | (m12 << 8) | lo8;
    const float rc = fmaxf(kval(ck), 0.f);

    // ---- Final pass over side buffer: last-bin winners and ties ----
    for (unsigned s = 0; s < sit; s++) {
        unsigned j = gid + s * NTHR_SEL;
        if (j < ns) {
            unsigned key = g_side_key[j];
            if ((key >> 8) == ((b12 << 12) | m12)) {
                unsigned lo = key & 0xFFu;
                if (lo > lo8) out[g_side_idx[j]] = fmaxf(kval(key), 0.f);
                else if (lo == lo8) {
                    if (!ambig) out[g_side_idx[j]] = rc;
                    else {
                        unsigned p = atomicAdd(&g_eq_cnt, 1u);
                        if (p < EQCAP) g_eq_idx[p] = g_side_idx[j];
                    }
                }
            }
        }
    }
    if (gid == 0) out[ntot] = (1.0f - EMA_E) * thr[0] + EMA_E * rc;
    if (gid < 256) g_hist8[gid] = 0;                          // re-zero

    // ---- Optional ambiguity path: one extra barrier + block-0 fixup ----
    if (ambig) {
        grid_bar(base + 4 * NB_SEL);                          // bar4
        if (blockIdx.x == 0) {
            // JAX tie-break: lowest flat index wins among equal-valued elems.
            unsigned ne = min(g_eq_cnt, EQCAP);
            __shared__ unsigned smin[256];
            __shared__ unsigned sbest;
            for (unsigned sel = 0; sel < need; sel++) {
                unsigned m = 0xFFFFFFFFu;
                for (unsigned j = t; j < ne; j += NT) m = min(m, g_eq_idx[j]);
                smin[t] = m;
                __syncthreads();
                for (int d = 128; d > 0; d >>= 1) {
                    if (t < d) smin[t] = min(smin[t], smin[t + d]);
                    __syncthreads();
                }
                if (t == 0) sbest = smin[0];
                __syncthreads();
                unsigned best = sbest;
                if (best == 0xFFFFFFFFu) break;
                for (unsigned j = t; j < ne; j += NT)
                    if (g_eq_idx[j] == best) g_eq_idx[j] = 0xFFFFFFFFu;
                if (t == 0) out[best] = rc;
                __syncthreads();
            }
        }
    }
    if (blockIdx.x == 0 && t == 0)
        g_base = base + (ambig ? 4u : 3u) * NB_SEL;
}

// ---------------------------------------------------------------------------
extern "C" void kernel_launch(void* const* d_in, const int* in_sizes, int n_in,
                              void* d_out, int out_size) {
    const float* x   = (const float*)d_in[0];
    const float* thr = (const float*)d_in[1];
    float* out = (float*)d_out;

    int n = in_sizes[0];
    int n4 = n / 4;
    int ntot = out_size - 1;   // threshold in last output slot

    k_sample<<<NBS, NT>>>((const float4*)x, n4);

    int nchunks = (n4 + CHUNK_F4 - 1) / CHUNK_F4;
    k_main<<<nchunks, NT>>>((const float4*)x, (float4*)out, n4);

    k_select<<<NB_SEL, NT>>>(thr, out, ntot);
}